// round 4
// baseline (speedup 1.0000x reference)
#include <cuda_runtime.h>

// Problem: B=2, 128^3 grid, C=3, 7 scaling-and-squaring steps.
#define D 128
#define DMASK 127
#define D3 (D * D * D)          // 2097152
#define NVOX (2 * D3)           // 4194304 voxels (B=2)
#define NTHREADS 256
#define NBLOCKS (NVOX / NTHREADS)

// Two SoA ping-pong buffers, 48 MB each. Layout: [comp][b*D3 + x*D*D + y*D + z].
__device__ float gA[3 * NVOX];
__device__ float gB[3 * NVOX];

// ---------------------------------------------------------------------------
// Transpose + scale: AoS dvf (float3 per voxel) -> SoA planes in gA, * 2^-7.
// ---------------------------------------------------------------------------
__global__ __launch_bounds__(NTHREADS) void transpose_scale_kernel(
    const float4* __restrict__ in4)
{
    const int i = blockIdx.x * NTHREADS + threadIdx.x;   // i < 3*NVOX/4
    const float s = 1.0f / 128.0f;                       // 2^-7, exact
    float4 v = in4[i];
    float vals[4] = {v.x, v.y, v.z, v.w};
    const int f = 4 * i;
    #pragma unroll
    for (int j = 0; j < 4; j++) {
        const int ff  = f + j;
        const int vox = ff / 3;
        const int c   = ff - 3 * vox;
        gA[c * NVOX + vox] = s * vals[j];
    }
}

// ---------------------------------------------------------------------------
// One squaring step, SoA -> SoA (or SoA -> AoS d_out on the last step).
// SRC: 1 = gA, 2 = gB.   DST: 0 = external AoS, 1 = gA, 2 = gB.
// All 24 gather loads are issued back-to-back into live registers (max MLP),
// then consumed by the FMA tree. launch_bounds(256,5) raises the reg budget
// to ~51 so nothing spills or serializes.
// ---------------------------------------------------------------------------
template <int SRC, int DST>
__global__ __launch_bounds__(NTHREADS, 5) void step_soa_kernel(
    float* __restrict__ ext_out)
{
    const float* __restrict__ sx = (SRC == 1) ? gA : gB;
    const float* __restrict__ sy = sx + NVOX;
    const float* __restrict__ sz = sx + 2 * NVOX;

    const int idx = blockIdx.x * NTHREADS + threadIdx.x;

    const int z = idx & DMASK;
    const int y = (idx >> 7) & DMASK;
    const int x = (idx >> 14) & DMASK;
    const int bbase = (idx >> 21) * D3;

    // Center displacement (coalesced).
    const float vx = sx[idx];
    const float vy = sy[idx];
    const float vz = sz[idx];

    const float lx = (float)x + vx;
    const float ly = (float)y + vy;
    const float lz = (float)z + vz;

    const float fx = floorf(lx), fy = floorf(ly), fz = floorf(lz);
    const float wx1 = lx - fx, wy1 = ly - fy, wz1 = lz - fz;
    const float wx0 = 1.0f - wx1, wy0 = 1.0f - wy1, wz0 = 1.0f - wz1;

    const int ix = (int)fx, iy = (int)fy, iz = (int)fz;

    // Clip corner indices; weights stay unclipped (matches reference).
    const int ix0 = min(max(ix,     0), DMASK);
    const int ix1 = min(max(ix + 1, 0), DMASK);
    const int iy0 = min(max(iy,     0), DMASK);
    const int iy1 = min(max(iy + 1, 0), DMASK);
    const int iz0 = min(max(iz,     0), DMASK);
    const int iz1 = min(max(iz + 1, 0), DMASK);

    const int X0 = bbase + ix0 * (D * D);
    const int X1 = bbase + ix1 * (D * D);
    const int Y0 = iy0 * D;
    const int Y1 = iy1 * D;

    // 8 corner linear indices.
    const int l000 = X0 + Y0 + iz0;
    const int l001 = X0 + Y0 + iz1;
    const int l010 = X0 + Y1 + iz0;
    const int l011 = X0 + Y1 + iz1;
    const int l100 = X1 + Y0 + iz0;
    const int l101 = X1 + Y0 + iz1;
    const int l110 = X1 + Y1 + iz0;
    const int l111 = X1 + Y1 + iz1;

    // Batch all 24 gathers: independent loads, all in flight together.
    const float x000 = __ldg(sx + l000), x001 = __ldg(sx + l001);
    const float x010 = __ldg(sx + l010), x011 = __ldg(sx + l011);
    const float x100 = __ldg(sx + l100), x101 = __ldg(sx + l101);
    const float x110 = __ldg(sx + l110), x111 = __ldg(sx + l111);

    const float y000 = __ldg(sy + l000), y001 = __ldg(sy + l001);
    const float y010 = __ldg(sy + l010), y011 = __ldg(sy + l011);
    const float y100 = __ldg(sy + l100), y101 = __ldg(sy + l101);
    const float y110 = __ldg(sy + l110), y111 = __ldg(sy + l111);

    const float z000 = __ldg(sz + l000), z001 = __ldg(sz + l001);
    const float z010 = __ldg(sz + l010), z011 = __ldg(sz + l011);
    const float z100 = __ldg(sz + l100), z101 = __ldg(sz + l101);
    const float z110 = __ldg(sz + l110), z111 = __ldg(sz + l111);

    // 8 trilinear weights.
    const float w00 = wx0 * wy0;
    const float w01 = wx0 * wy1;
    const float w10 = wx1 * wy0;
    const float w11 = wx1 * wy1;
    const float w000 = w00 * wz0, w001 = w00 * wz1;
    const float w010 = w01 * wz0, w011 = w01 * wz1;
    const float w100 = w10 * wz0, w101 = w10 * wz1;
    const float w110 = w11 * wz0, w111 = w11 * wz1;

    float ax, ay, az;
    ax = w000 * x000; ay = w000 * y000; az = w000 * z000;
    ax = fmaf(w001, x001, ax); ay = fmaf(w001, y001, ay); az = fmaf(w001, z001, az);
    ax = fmaf(w010, x010, ax); ay = fmaf(w010, y010, ay); az = fmaf(w010, z010, az);
    ax = fmaf(w011, x011, ax); ay = fmaf(w011, y011, ay); az = fmaf(w011, z011, az);
    ax = fmaf(w100, x100, ax); ay = fmaf(w100, y100, ay); az = fmaf(w100, z100, az);
    ax = fmaf(w101, x101, ax); ay = fmaf(w101, y101, ay); az = fmaf(w101, z101, az);
    ax = fmaf(w110, x110, ax); ay = fmaf(w110, y110, ay); az = fmaf(w110, z110, az);
    ax = fmaf(w111, x111, ax); ay = fmaf(w111, y111, ay); az = fmaf(w111, z111, az);

    const float ox = vx + ax;
    const float oy = vy + ay;
    const float oz = vz + az;

    if (DST == 0) {
        // Final step: AoS float3 into d_out.
        float* o = ext_out + 3 * idx;
        o[0] = ox; o[1] = oy; o[2] = oz;
    } else {
        float* dx = (DST == 1) ? gA : gB;
        dx[idx]            = ox;
        dx[NVOX + idx]     = oy;
        dx[2 * NVOX + idx] = oz;
    }
}

extern "C" void kernel_launch(void* const* d_in, const int* in_sizes, int n_in,
                              void* d_out, int out_size)
{
    const float4* dvf4 = (const float4*)d_in[0];
    float* out = (float*)d_out;

    // AoS dvf -> scaled SoA in gA (ddf0 = dvf * 2^-7, exact).
    transpose_scale_kernel<<<(3 * NVOX / 4) / NTHREADS, NTHREADS>>>(dvf4);

    // 7 squaring steps, ping-pong; final step writes AoS into d_out.
    step_soa_kernel<1, 2><<<NBLOCKS, NTHREADS>>>(nullptr);  // 1: A -> B
    step_soa_kernel<2, 1><<<NBLOCKS, NTHREADS>>>(nullptr);  // 2: B -> A
    step_soa_kernel<1, 2><<<NBLOCKS, NTHREADS>>>(nullptr);  // 3: A -> B
    step_soa_kernel<2, 1><<<NBLOCKS, NTHREADS>>>(nullptr);  // 4: B -> A
    step_soa_kernel<1, 2><<<NBLOCKS, NTHREADS>>>(nullptr);  // 5: A -> B
    step_soa_kernel<2, 1><<<NBLOCKS, NTHREADS>>>(nullptr);  // 6: B -> A
    step_soa_kernel<1, 0><<<NBLOCKS, NTHREADS>>>(out);      // 7: A -> d_out
}